// round 8
// baseline (speedup 1.0000x reference)
#include <cuda_runtime.h>
#include <cuda_fp16.h>
#include <cstdint>

#define NN   50000
#define NE   800000
#define NG   64
#define CH   64
#define INCH 128
#define SCAN_B 1024
#define NB   ((NN + SCAN_B - 1) / SCAN_B)   // 49

// ---------------- scratch (static device globals; no allocation) -------------
// everything needing zero-init lives in ONE struct -> one memset node
struct ZeroBlk {
    unsigned long long pd[NN];          // count<<40 | wdeg fixed-point
    unsigned maxk[NG * CH];             // ukey-max accumulator (0 = -inf)
    float    sum[NG * CH];
    float    cnt[NG];
    unsigned done;
};
__device__ ZeroBlk g_z;
__device__ float g_dinv[NN];
__device__ int   g_rowptr[NN + 1];
__device__ int   g_fill[NN];
__device__ int   g_bsum[64];
__device__ int2  g_edge[NE];                   // CSR-sorted (src, w-bits)
__device__ __align__(16) __half g_h[NN * CH];  // h' = dinv * (act @ W), fp16
__device__ __align__(16) float g_act[NN * CH]; // tanh(layer output), fp32

// ---------------- helpers ----------------------------------------------------
__device__ __forceinline__ float acc_tanh(float x) {
    float e = __expf(-2.0f * fabsf(x));
    float t = __fdividef(1.0f - e, 1.0f + e);
    return copysignf(t, x);
}
// monotonic unsigned key: 0 == "below any real float"
__device__ __forceinline__ unsigned ukey(float f) {
    unsigned u = __float_as_uint(f);
    return (u & 0x80000000u) ? ~u : (u | 0x80000000u);
}
__device__ __forceinline__ float udec(unsigned u) {
    return __uint_as_float((u & 0x80000000u) ? (u & 0x7FFFFFFFu) : ~u);
}

#define FMA2(d, a, b) asm("fma.rn.f32x2 %0, %1, %2, %0;" : "+l"(d) : "l"(a), "l"(b))
__device__ __forceinline__ unsigned long long pack2(float x) {
    unsigned long long r;
    unsigned xi = __float_as_uint(x);
    asm("mov.b64 %0, {%1, %1};" : "=l"(r) : "r"(xi));
    return r;
}
__device__ __forceinline__ float2 unpack2(unsigned long long v) {
    unsigned lo, hi;
    asm("mov.b64 {%0, %1}, %2;" : "=r"(lo), "=r"(hi) : "l"(v));
    return make_float2(__uint_as_float(lo), __uint_as_float(hi));
}
__device__ __forceinline__ unsigned h2_to_u(__half2 h) {
    return *reinterpret_cast<unsigned*>(&h);
}
__device__ __forceinline__ __half2 u_to_h2(unsigned u) {
    return *reinterpret_cast<__half2*>(&u);
}

// ---------------- preprocessing ----------------------------------------------
// one 64-bit RED per edge: count in bits [40..], wdeg as 2^21 fixed point below
__global__ void k_pre_deg(const int* __restrict__ ei, const float* __restrict__ w) {
    int e = blockIdx.x * blockDim.x + threadIdx.x;
    if (e < NE) {
        int dst = ei[NE + e];
        unsigned long long v = (1ull << 40) |
            (unsigned long long)__float2uint_rn(w[e] * 2097152.0f);
        atomicAdd(&g_z.pd[dst], v);
    }
}

// warp-shuffle scan over 1024 deg; writes pre-carry rowptr AND fill; computes dinv
__global__ void k_scan_block() {
    __shared__ int wsum[32];
    int tid = threadIdx.x;
    int i   = blockIdx.x * SCAN_B + tid;
    int lane = tid & 31, wid = tid >> 5;
    unsigned long long pd = (i < NN) ? g_z.pd[i] : 0ull;
    int v = (int)(pd >> 40);
    int s = v;
#pragma unroll
    for (int o = 1; o < 32; o <<= 1) {
        int t = __shfl_up_sync(0xFFFFFFFFu, s, o);
        if (lane >= o) s += t;
    }
    if (lane == 31) wsum[wid] = s;
    __syncthreads();
    if (wid == 0) {
        int ws = wsum[lane];
#pragma unroll
        for (int o = 1; o < 32; o <<= 1) {
            int t = __shfl_up_sync(0xFFFFFFFFu, ws, o);
            if (lane >= o) ws += t;
        }
        wsum[lane] = ws;
    }
    __syncthreads();
    int off = wid ? wsum[wid - 1] : 0;
    if (i < NN) {
        int rp = off + s - v;          // exclusive, pre-carry
        g_rowptr[i] = rp;
        g_fill[i]   = rp;
        float wdeg = (float)(pd & ((1ull << 40) - 1ull)) * (1.0f / 2097152.0f);
        g_dinv[i] = rsqrtf(wdeg + 1.0f);   // +1 self-loop weight
    }
    if (tid == SCAN_B - 1) g_bsum[blockIdx.x] = off + s;
}

// place + carry apply (each block redoes the tiny 49-elem carry scan)
__global__ void k_place(const int* __restrict__ ei, const float* __restrict__ w) {
    __shared__ int sc[64];
    int tid = threadIdx.x;
    if (tid < 32) {
        int v0 = (2 * tid     < NB) ? g_bsum[2 * tid]     : 0;
        int v1 = (2 * tid + 1 < NB) ? g_bsum[2 * tid + 1] : 0;
        int p = v0 + v1;
        int s = p;
#pragma unroll
        for (int o = 1; o < 32; o <<= 1) {
            int t = __shfl_up_sync(0xFFFFFFFFu, s, o);
            if (tid >= o) s += t;
        }
        sc[2 * tid]     = s - p;
        sc[2 * tid + 1] = s - p + v0;
    }
    __syncthreads();
    int e = blockIdx.x * blockDim.x + tid;
    if (e < NE) {
        int src = ei[e];
        int dst = ei[NE + e];
        int pos = atomicAdd(&g_fill[dst], 1) + sc[dst >> 10];
        g_edge[pos] = make_int2(src, __float_as_int(w[e]));   // raw weight
    }
    // finalize rowptr for the gather (carry applied exactly once here)
    if (e < NN) g_rowptr[e] += sc[e >> 10];
    if (e == 0) g_rowptr[NN] = NE;
}

// ------- GEMM: h' = dinv * (A @ W)  (f32x2 FMA), fp16 output -------------------
// 256 threads; block = 64 rows x 64 cols; thread = 4 rows x 4 cols.
template <int K, bool FROM_ACT>
__global__ void k_gemm(const float* __restrict__ in, const float* __restrict__ W) {
    __shared__ __align__(16) float sA[64 * 68];   // [row][k], pad 68
    __shared__ __align__(16) float sW[64 * 64];   // [k][col]

    const int tid  = threadIdx.x;
    const int row0 = blockIdx.x * 64;
    const int rowg = tid >> 4;    // 0..15, 4 rows each
    const int colg = tid & 15;    // 0..15, 4 cols each

    const float* A = FROM_ACT ? (const float*)g_act : in;

    unsigned long long acc[4][2] = {{0ull,0ull},{0ull,0ull},{0ull,0ull},{0ull,0ull}};

    for (int kc = 0; kc < K; kc += 64) {
#pragma unroll
        for (int idx = tid; idx < 64 * 16; idx += 256) {
            int rr = idx >> 4, k4 = (idx & 15) * 4;
            int grow = row0 + rr;
            float4 v = make_float4(0.f, 0.f, 0.f, 0.f);
            if (grow < NN) v = *(const float4*)(A + (size_t)grow * K + kc + k4);
            *(float4*)(sA + rr * 68 + k4) = v;
        }
#pragma unroll
        for (int idx = tid; idx < 64 * 16; idx += 256) {
            int rr = idx >> 4, c4 = (idx & 15) * 4;
            *(float4*)(sW + rr * 64 + c4) = *(const float4*)(W + (size_t)(kc + rr) * 64 + c4);
        }
        __syncthreads();

#pragma unroll
        for (int k = 0; k < 64; ++k) {
            const ulonglong2 wv = *(const ulonglong2*)(sW + k * 64 + colg * 4);
            unsigned long long pa0 = pack2(sA[(rowg * 4 + 0) * 68 + k]);
            unsigned long long pa1 = pack2(sA[(rowg * 4 + 1) * 68 + k]);
            unsigned long long pa2 = pack2(sA[(rowg * 4 + 2) * 68 + k]);
            unsigned long long pa3 = pack2(sA[(rowg * 4 + 3) * 68 + k]);
            FMA2(acc[0][0], pa0, wv.x); FMA2(acc[0][1], pa0, wv.y);
            FMA2(acc[1][0], pa1, wv.x); FMA2(acc[1][1], pa1, wv.y);
            FMA2(acc[2][0], pa2, wv.x); FMA2(acc[2][1], pa2, wv.y);
            FMA2(acc[3][0], pa3, wv.x); FMA2(acc[3][1], pa3, wv.y);
        }
        __syncthreads();
    }

    int row = row0 + rowg * 4;
#pragma unroll
    for (int i = 0; i < 4; ++i) {
        if (row + i < NN) {
            float dv = g_dinv[row + i];
            float2 lo = unpack2(acc[i][0]);
            float2 hi = unpack2(acc[i][1]);
            lo.x *= dv; lo.y *= dv; hi.x *= dv; hi.y *= dv;
            uint2 st;
            st.x = h2_to_u(__float22half2_rn(lo));
            st.y = h2_to_u(__float22half2_rn(hi));
            *(uint2*)(g_h + (size_t)(row + i) * CH + colg * 4) = st;
        }
    }
}

// --- gather: act[i] = tanh(b + dv_i*(sum_e w_e*h'[src] + h'[i])) ---------------
// one warp per node; 4 edges per iteration; lane = (quad, c8): 8 fp16 channels.
__global__ void k_gather(const float* __restrict__ b) {
    int warp = (blockIdx.x * blockDim.x + threadIdx.x) >> 5;
    int lane = threadIdx.x & 31;
    if (warp >= NN) return;
    const int node = warp;
    const int beg  = g_rowptr[node];
    const int deg  = g_rowptr[node + 1] - beg;
    const int quad = lane >> 3;       // 0..3: which edge of the group
    const int c8   = (lane & 7) * 8;  // fp16 channel base (16B aligned)

    float a0=0.f,a1=0.f,a2=0.f,a3=0.f,a4=0.f,a5=0.f,a6=0.f,a7=0.f;
    for (int ch = 0; ch < deg; ch += 32) {
        int rem = deg - ch;
        int n = rem < 32 ? rem : 32;
        int s = node; float nm = 0.0f;     // inactive lanes: nm=0 contributes nothing
        if (lane < n) {
            int2 e = g_edge[beg + ch + lane];
            s = e.x; nm = __int_as_float(e.y);
        }
        int nq = (n + 3) >> 2;
#pragma unroll 4
        for (int j = 0; j < nq; ++j) {
            int   se = __shfl_sync(0xFFFFFFFFu, s,  4 * j + quad);
            float ne = __shfl_sync(0xFFFFFFFFu, nm, 4 * j + quad);
            uint4 hv = *(const uint4*)(g_h + (size_t)se * CH + c8);
            float2 f0 = __half22float2(u_to_h2(hv.x));
            float2 f1 = __half22float2(u_to_h2(hv.y));
            float2 f2 = __half22float2(u_to_h2(hv.z));
            float2 f3 = __half22float2(u_to_h2(hv.w));
            a0 += ne * f0.x; a1 += ne * f0.y; a2 += ne * f1.x; a3 += ne * f1.y;
            a4 += ne * f2.x; a5 += ne * f2.y; a6 += ne * f3.x; a7 += ne * f3.y;
        }
    }
    // reduce across the 4 quads
#pragma unroll
    for (int o = 8; o <= 16; o <<= 1) {
        a0 += __shfl_xor_sync(0xFFFFFFFFu, a0, o);
        a1 += __shfl_xor_sync(0xFFFFFFFFu, a1, o);
        a2 += __shfl_xor_sync(0xFFFFFFFFu, a2, o);
        a3 += __shfl_xor_sync(0xFFFFFFFFu, a3, o);
        a4 += __shfl_xor_sync(0xFFFFFFFFu, a4, o);
        a5 += __shfl_xor_sync(0xFFFFFFFFu, a5, o);
        a6 += __shfl_xor_sync(0xFFFFFFFFu, a6, o);
        a7 += __shfl_xor_sync(0xFFFFFFFFu, a7, o);
    }

    if (quad == 0) {   // lanes 0..7 each own 8 channels
        float dv = g_dinv[node];
        uint4 hu = *(const uint4*)(g_h + (size_t)node * CH + c8);
        float2 h0 = __half22float2(u_to_h2(hu.x));
        float2 h1 = __half22float2(u_to_h2(hu.y));
        float2 h2 = __half22float2(u_to_h2(hu.z));
        float2 h3 = __half22float2(u_to_h2(hu.w));
        float4 bb0 = *(const float4*)(b + c8);
        float4 bb1 = *(const float4*)(b + c8 + 4);
        float4 o0, o1;
        o0.x = acc_tanh(bb0.x + dv * (a0 + h0.x));
        o0.y = acc_tanh(bb0.y + dv * (a1 + h0.y));
        o0.z = acc_tanh(bb0.z + dv * (a2 + h1.x));
        o0.w = acc_tanh(bb0.w + dv * (a3 + h1.y));
        o1.x = acc_tanh(bb1.x + dv * (a4 + h2.x));
        o1.y = acc_tanh(bb1.y + dv * (a5 + h2.y));
        o1.z = acc_tanh(bb1.z + dv * (a6 + h3.x));
        o1.w = acc_tanh(bb1.w + dv * (a7 + h3.y));
        *(float4*)(g_act + (size_t)node * CH + c8)     = o0;
        *(float4*)(g_act + (size_t)node * CH + c8 + 4) = o1;
    }
}

// ---------------- pooling + fused head (g_z memset to 0) -----------------------
__device__ __forceinline__ void pool_flush(int g, int c, float mx, float sm, int cnt) {
    if (g < 0) return;
    atomicMax(&g_z.maxk[g * CH + c], ukey(mx));
    atomicAdd(&g_z.sum[g * CH + c], sm);
    if (c == 0) atomicAdd(&g_z.cnt[g], (float)cnt);
}

__global__ void k_pool(const int* __restrict__ batch,
                       const float* __restrict__ Wout,
                       const float* __restrict__ bout,
                       float* __restrict__ out) {
    int tid = threadIdx.x;
    int c  = tid & 63;
    int rs = tid >> 6;           // 0..3
    int base = blockIdx.x * 64;

    int curg = -1; float mx = -3.4e38f, sm = 0.0f; int cnt = 0;
    for (int r = rs; r < 64; r += 4) {
        int node = base + r;
        if (node >= NN) break;
        int g = batch[node];
        float v = g_act[(size_t)node * CH + c];
        if (g != curg) {
            pool_flush(curg, c, mx, sm, cnt);
            curg = g; mx = v; sm = v; cnt = 1;
        } else {
            mx = fmaxf(mx, v); sm += v; cnt++;
        }
    }
    pool_flush(curg, c, mx, sm, cnt);

    // last-block head
    __threadfence();
    __shared__ int s_last;
    __syncthreads();
    if (tid == 0) {
        unsigned t = atomicAdd(&g_z.done, 1u);
        s_last = (t == gridDim.x - 1) ? 1 : 0;
    }
    __syncthreads();
    if (!s_last) return;
    __threadfence();

    __shared__ float sh[8];
    int gl = tid >> 6;                 // 0..3
#pragma unroll
    for (int pass = 0; pass < NG / 4; ++pass) {
        int g = pass * 4 + gl;
        float mxv  = udec(g_z.maxk[g * CH + c]);
        float mean = g_z.sum[g * CH + c] / fmaxf(g_z.cnt[g], 1.0f);
        float v = mxv * Wout[c] + mean * Wout[CH + c];
#pragma unroll
        for (int o = 16; o > 0; o >>= 1) v += __shfl_down_sync(0xFFFFFFFFu, v, o);
        if ((tid & 31) == 0) sh[tid >> 5] = v;
        __syncthreads();
        if (tid < 4) out[pass * 4 + tid] = sh[2 * tid] + sh[2 * tid + 1] + bout[0];
        __syncthreads();
    }
}

// ---------------- launch -------------------------------------------------------
extern "C" void kernel_launch(void* const* d_in, const int* in_sizes, int n_in,
                              void* d_out, int out_size) {
    const float* x     = (const float*)d_in[0];
    const int*   ei    = (const int*)  d_in[1];
    const float* ea    = (const float*)d_in[2];
    const int*   batch = (const int*)  d_in[3];
    const float* W0 = (const float*)d_in[4];  const float* b0 = (const float*)d_in[5];
    const float* W1 = (const float*)d_in[6];  const float* b1 = (const float*)d_in[7];
    const float* W2 = (const float*)d_in[8];  const float* b2 = (const float*)d_in[9];
    const float* W3 = (const float*)d_in[10]; const float* b3 = (const float*)d_in[11];
    const float* Wout = (const float*)d_in[12];
    const float* bout = (const float*)d_in[13];
    float* out = (float*)d_out;

    void* z_addr = nullptr;
    cudaGetSymbolAddress(&z_addr, g_z);

    const int TB = 256;
    const int gemm_blocks   = (NN + 63) / 64;                 // 782
    const int gather_blocks = (NN * 32 + TB - 1) / TB;        // 6250

    // one zero-init node for all accumulators
    cudaMemsetAsync(z_addr, 0, sizeof(ZeroBlk), 0);

    // preprocessing + CSR build (once; reused by all 4 layers)
    k_pre_deg <<<(NE + TB - 1) / TB, TB>>>(ei, ea);
    k_scan_block<<<NB, SCAN_B>>>();
    k_place<<<(NE + TB - 1) / TB, TB>>>(ei, ea);

    // layer 0: 128 -> 64 from x
    k_gemm<INCH, false><<<gemm_blocks, TB>>>(x, W0);
    k_gather<<<gather_blocks, TB>>>(b0);
    // layers 1..3: 64 -> 64 from g_act (already tanh'd), resolved in device code
    k_gemm<CH, true><<<gemm_blocks, TB>>>(nullptr, W1);
    k_gather<<<gather_blocks, TB>>>(b1);
    k_gemm<CH, true><<<gemm_blocks, TB>>>(nullptr, W2);
    k_gather<<<gather_blocks, TB>>>(b2);
    k_gemm<CH, true><<<gemm_blocks, TB>>>(nullptr, W3);
    k_gather<<<gather_blocks, TB>>>(b3);

    // pooling + head (fused; last block writes out)
    k_pool<<<gemm_blocks, TB>>>(batch, Wout, bout, out);
}

// round 9
// speedup vs baseline: 1.1284x; 1.1284x over previous
#include <cuda_runtime.h>
#include <cuda_fp16.h>
#include <cstdint>

#define NN   50000
#define NE   800000
#define NG   64
#define CH   64
#define INCH 128
#define SCAN_B 1024
#define NB   ((NN + SCAN_B - 1) / SCAN_B)   // 49

// ---------------- scratch (static device globals; no allocation) -------------
struct ZeroBlk {
    unsigned long long pd[NN];          // count<<40 | wdeg fixed-point
    unsigned maxk[NG * CH];             // ukey-max accumulator (0 = -inf)
    float    sum[NG * CH];
    float    cnt[NG];
    unsigned done;
};
__device__ ZeroBlk g_z;
__device__ float g_dinv[NN];
__device__ int   g_rowptr[NN + 1];
__device__ int   g_fill[NN];
__device__ int   g_bsum[64];
__device__ int2  g_edge[NE];                   // CSR-sorted (src, w-bits)
__device__ __align__(16) __half g_h[NN * CH];  // h' = dinv * (act @ W), fp16
__device__ __align__(16) float g_act[NN * CH]; // tanh(layer output), fp32

// ---------------- helpers ----------------------------------------------------
__device__ __forceinline__ float acc_tanh(float x) {
    float e = __expf(-2.0f * fabsf(x));
    float t = __fdividef(1.0f - e, 1.0f + e);
    return copysignf(t, x);
}
__device__ __forceinline__ unsigned ukey(float f) {
    unsigned u = __float_as_uint(f);
    return (u & 0x80000000u) ? ~u : (u | 0x80000000u);
}
__device__ __forceinline__ float udec(unsigned u) {
    return __uint_as_float((u & 0x80000000u) ? (u & 0x7FFFFFFFu) : ~u);
}

#define FMA2(d, a, b) asm("fma.rn.f32x2 %0, %1, %2, %0;" : "+l"(d) : "l"(a), "l"(b))
__device__ __forceinline__ unsigned long long pack2(float x) {
    unsigned long long r;
    unsigned xi = __float_as_uint(x);
    asm("mov.b64 %0, {%1, %1};" : "=l"(r) : "r"(xi));
    return r;
}
__device__ __forceinline__ float2 unpack2(unsigned long long v) {
    unsigned lo, hi;
    asm("mov.b64 {%0, %1}, %2;" : "=r"(lo), "=r"(hi) : "l"(v));
    return make_float2(__uint_as_float(lo), __uint_as_float(hi));
}
__device__ __forceinline__ unsigned h2_to_u(__half2 h) {
    return *reinterpret_cast<unsigned*>(&h);
}
__device__ __forceinline__ __half2 u_to_h2(unsigned u) {
    return *reinterpret_cast<__half2*>(&u);
}

// ---------------- preprocessing ----------------------------------------------
__global__ void k_pre_deg(const int* __restrict__ ei, const float* __restrict__ w) {
    int e = blockIdx.x * blockDim.x + threadIdx.x;
    if (e < NE) {
        int dst = ei[NE + e];
        unsigned long long v = (1ull << 40) |
            (unsigned long long)__float2uint_rn(w[e] * 2097152.0f);
        atomicAdd(&g_z.pd[dst], v);
    }
}

__global__ void k_scan_block() {
    __shared__ int wsum[32];
    int tid = threadIdx.x;
    int i   = blockIdx.x * SCAN_B + tid;
    int lane = tid & 31, wid = tid >> 5;
    unsigned long long pd = (i < NN) ? g_z.pd[i] : 0ull;
    int v = (int)(pd >> 40);
    int s = v;
#pragma unroll
    for (int o = 1; o < 32; o <<= 1) {
        int t = __shfl_up_sync(0xFFFFFFFFu, s, o);
        if (lane >= o) s += t;
    }
    if (lane == 31) wsum[wid] = s;
    __syncthreads();
    if (wid == 0) {
        int ws = wsum[lane];
#pragma unroll
        for (int o = 1; o < 32; o <<= 1) {
            int t = __shfl_up_sync(0xFFFFFFFFu, ws, o);
            if (lane >= o) ws += t;
        }
        wsum[lane] = ws;
    }
    __syncthreads();
    int off = wid ? wsum[wid - 1] : 0;
    if (i < NN) {
        int rp = off + s - v;          // exclusive, pre-carry
        g_rowptr[i] = rp;
        g_fill[i]   = rp;
        float wdeg = (float)(pd & ((1ull << 40) - 1ull)) * (1.0f / 2097152.0f);
        g_dinv[i] = rsqrtf(wdeg + 1.0f);   // +1 self-loop weight
    }
    if (tid == SCAN_B - 1) g_bsum[blockIdx.x] = off + s;
}

// place + carry apply (each block redoes the tiny 49-elem carry scan)
__global__ void k_place(const int* __restrict__ ei, const float* __restrict__ w) {
    __shared__ int sc[64];
    int tid = threadIdx.x;
    if (tid < 32) {
        int v0 = (2 * tid     < NB) ? g_bsum[2 * tid]     : 0;
        int v1 = (2 * tid + 1 < NB) ? g_bsum[2 * tid + 1] : 0;
        int p = v0 + v1;
        int s = p;
#pragma unroll
        for (int o = 1; o < 32; o <<= 1) {
            int t = __shfl_up_sync(0xFFFFFFFFu, s, o);
            if (tid >= o) s += t;
        }
        sc[2 * tid]     = s - p;
        sc[2 * tid + 1] = s - p + v0;
    }
    __syncthreads();
    int e = blockIdx.x * blockDim.x + tid;
    if (e < NE) {
        int src = ei[e];
        int dst = ei[NE + e];
        int pos = atomicAdd(&g_fill[dst], 1) + sc[dst >> 10];
        g_edge[pos] = make_int2(src, __float_as_int(w[e]));   // raw weight
    }
    if (e < NN) g_rowptr[e] += sc[e >> 10];
    if (e == 0) g_rowptr[NN] = NE;
}

// ------- GEMM: h' = dinv * (A @ W)  (f32x2 FMA, k-vectorized LDS) --------------
// 256 threads, 4 CTAs/SM; block = 64 rows x 64 cols; thread = 4 rows x 4 cols.
template <int K, bool FROM_ACT>
__global__ void __launch_bounds__(256, 4)
k_gemm(const float* __restrict__ in, const float* __restrict__ W) {
    __shared__ __align__(16) float sA[64 * 68];   // [row][k], stride 272B (16B mult)
    __shared__ __align__(16) float sW[64 * 64];   // [k][col]

    const int tid  = threadIdx.x;
    const int row0 = blockIdx.x * 64;
    const int rowg = tid >> 4;    // 0..15, 4 rows each
    const int colg = tid & 15;    // 0..15, 4 cols each

    const float* A = FROM_ACT ? (const float*)g_act : in;

    unsigned long long acc[4][2] = {{0ull,0ull},{0ull,0ull},{0ull,0ull},{0ull,0ull}};

    for (int kc = 0; kc < K; kc += 64) {
#pragma unroll
        for (int idx = tid; idx < 64 * 16; idx += 256) {
            int rr = idx >> 4, k4 = (idx & 15) * 4;
            int grow = row0 + rr;
            float4 v = make_float4(0.f, 0.f, 0.f, 0.f);
            if (grow < NN) v = *(const float4*)(A + (size_t)grow * K + kc + k4);
            *(float4*)(sA + rr * 68 + k4) = v;
        }
#pragma unroll
        for (int idx = tid; idx < 64 * 16; idx += 256) {
            int rr = idx >> 4, c4 = (idx & 15) * 4;
            *(float4*)(sW + rr * 64 + c4) = *(const float4*)(W + (size_t)(kc + rr) * 64 + c4);
        }
        __syncthreads();

#pragma unroll
        for (int k = 0; k < 64; k += 4) {
            // A: one LDS.128 per row covering k..k+3 (2 distinct addrs/warp -> broadcast)
            float4 a0 = *(const float4*)(sA + (rowg * 4 + 0) * 68 + k);
            float4 a1 = *(const float4*)(sA + (rowg * 4 + 1) * 68 + k);
            float4 a2 = *(const float4*)(sA + (rowg * 4 + 2) * 68 + k);
            float4 a3 = *(const float4*)(sA + (rowg * 4 + 3) * 68 + k);
#pragma unroll
            for (int j = 0; j < 4; ++j) {
                const ulonglong2 wv = *(const ulonglong2*)(sW + (k + j) * 64 + colg * 4);
                float e0 = j == 0 ? a0.x : j == 1 ? a0.y : j == 2 ? a0.z : a0.w;
                float e1 = j == 0 ? a1.x : j == 1 ? a1.y : j == 2 ? a1.z : a1.w;
                float e2 = j == 0 ? a2.x : j == 1 ? a2.y : j == 2 ? a2.z : a2.w;
                float e3 = j == 0 ? a3.x : j == 1 ? a3.y : j == 2 ? a3.z : a3.w;
                unsigned long long p0 = pack2(e0), p1 = pack2(e1);
                unsigned long long p2 = pack2(e2), p3 = pack2(e3);
                FMA2(acc[0][0], p0, wv.x); FMA2(acc[0][1], p0, wv.y);
                FMA2(acc[1][0], p1, wv.x); FMA2(acc[1][1], p1, wv.y);
                FMA2(acc[2][0], p2, wv.x); FMA2(acc[2][1], p2, wv.y);
                FMA2(acc[3][0], p3, wv.x); FMA2(acc[3][1], p3, wv.y);
            }
        }
        __syncthreads();
    }

    int row = row0 + rowg * 4;
#pragma unroll
    for (int i = 0; i < 4; ++i) {
        if (row + i < NN) {
            float dv = g_dinv[row + i];
            float2 lo = unpack2(acc[i][0]);
            float2 hi = unpack2(acc[i][1]);
            lo.x *= dv; lo.y *= dv; hi.x *= dv; hi.y *= dv;
            uint2 st;
            st.x = h2_to_u(__float22half2_rn(lo));
            st.y = h2_to_u(__float22half2_rn(hi));
            *(uint2*)(g_h + (size_t)(row + i) * CH + colg * 4) = st;
        }
    }
}

// --- gather: act[i] = tanh(b + dv_i*(sum_e w_e*h'[src] + h'[i])) ---------------
// one warp per node; 2 edges per iteration; lane = (half, c4): 4 fp16 channels.
__global__ void k_gather(const float* __restrict__ b) {
    int warp = (blockIdx.x * blockDim.x + threadIdx.x) >> 5;
    int lane = threadIdx.x & 31;
    if (warp >= NN) return;
    const int node = warp;
    const int beg  = g_rowptr[node];
    const int deg  = g_rowptr[node + 1] - beg;
    const int half = lane >> 4;
    const int c4   = (lane & 15) * 4;

    float ax = 0.f, ay = 0.f, az = 0.f, aw = 0.f;
    for (int ch = 0; ch < deg; ch += 32) {
        int rem = deg - ch;
        int n = rem < 32 ? rem : 32;
        int s = node; float nm = 0.0f;     // inactive lanes: nm=0 contributes nothing
        if (lane < n) {
            int2 e = g_edge[beg + ch + lane];
            s = e.x; nm = __int_as_float(e.y);
        }
        int npairs = (n + 1) >> 1;
#pragma unroll 4
        for (int j = 0; j < npairs; ++j) {
            int   se = __shfl_sync(0xFFFFFFFFu, s,  2 * j + half);
            float ne = __shfl_sync(0xFFFFFFFFu, nm, 2 * j + half);
            uint2 hv = *(const uint2*)(g_h + (size_t)se * CH + c4);
            float2 f0 = __half22float2(u_to_h2(hv.x));
            float2 f1 = __half22float2(u_to_h2(hv.y));
            ax += ne * f0.x; ay += ne * f0.y; az += ne * f1.x; aw += ne * f1.y;
        }
    }
    ax += __shfl_xor_sync(0xFFFFFFFFu, ax, 16);
    ay += __shfl_xor_sync(0xFFFFFFFFu, ay, 16);
    az += __shfl_xor_sync(0xFFFFFFFFu, az, 16);
    aw += __shfl_xor_sync(0xFFFFFFFFu, aw, 16);

    if (half == 0) {
        float dv = g_dinv[node];
        uint2 hu = *(const uint2*)(g_h + (size_t)node * CH + c4);
        float2 h0 = __half22float2(u_to_h2(hu.x));
        float2 h1 = __half22float2(u_to_h2(hu.y));
        float4 bb = *(const float4*)(b + c4);
        float4 o;
        o.x = acc_tanh(bb.x + dv * (ax + h0.x));
        o.y = acc_tanh(bb.y + dv * (ay + h0.y));
        o.z = acc_tanh(bb.z + dv * (az + h1.x));
        o.w = acc_tanh(bb.w + dv * (aw + h1.y));
        *(float4*)(g_act + (size_t)node * CH + c4) = o;
    }
}

// ---------------- pooling + fused head (g_z memset to 0) -----------------------
__device__ __forceinline__ void pool_flush(int g, int c, float mx, float sm, int cnt) {
    if (g < 0) return;
    atomicMax(&g_z.maxk[g * CH + c], ukey(mx));
    atomicAdd(&g_z.sum[g * CH + c], sm);
    if (c == 0) atomicAdd(&g_z.cnt[g], (float)cnt);
}

__global__ void k_pool(const int* __restrict__ batch,
                       const float* __restrict__ Wout,
                       const float* __restrict__ bout,
                       float* __restrict__ out) {
    int tid = threadIdx.x;
    int c  = tid & 63;
    int rs = tid >> 6;           // 0..3
    int base = blockIdx.x * 64;

    int curg = -1; float mx = -3.4e38f, sm = 0.0f; int cnt = 0;
    for (int r = rs; r < 64; r += 4) {
        int node = base + r;
        if (node >= NN) break;
        int g = batch[node];
        float v = g_act[(size_t)node * CH + c];
        if (g != curg) {
            pool_flush(curg, c, mx, sm, cnt);
            curg = g; mx = v; sm = v; cnt = 1;
        } else {
            mx = fmaxf(mx, v); sm += v; cnt++;
        }
    }
    pool_flush(curg, c, mx, sm, cnt);

    // last-block head
    __threadfence();
    __shared__ int s_last;
    __syncthreads();
    if (tid == 0) {
        unsigned t = atomicAdd(&g_z.done, 1u);
        s_last = (t == gridDim.x - 1) ? 1 : 0;
    }
    __syncthreads();
    if (!s_last) return;
    __threadfence();

    __shared__ float sh[8];
    int gl = tid >> 6;                 // 0..3
#pragma unroll
    for (int pass = 0; pass < NG / 4; ++pass) {
        int g = pass * 4 + gl;
        float mxv  = udec(g_z.maxk[g * CH + c]);
        float mean = g_z.sum[g * CH + c] / fmaxf(g_z.cnt[g], 1.0f);
        float v = mxv * Wout[c] + mean * Wout[CH + c];
#pragma unroll
        for (int o = 16; o > 0; o >>= 1) v += __shfl_down_sync(0xFFFFFFFFu, v, o);
        if ((tid & 31) == 0) sh[tid >> 5] = v;
        __syncthreads();
        if (tid < 4) out[pass * 4 + tid] = sh[2 * tid] + sh[2 * tid + 1] + bout[0];
        __syncthreads();
    }
}

// ---------------- launch -------------------------------------------------------
extern "C" void kernel_launch(void* const* d_in, const int* in_sizes, int n_in,
                              void* d_out, int out_size) {
    const float* x     = (const float*)d_in[0];
    const int*   ei    = (const int*)  d_in[1];
    const float* ea    = (const float*)d_in[2];
    const int*   batch = (const int*)  d_in[3];
    const float* W0 = (const float*)d_in[4];  const float* b0 = (const float*)d_in[5];
    const float* W1 = (const float*)d_in[6];  const float* b1 = (const float*)d_in[7];
    const float* W2 = (const float*)d_in[8];  const float* b2 = (const float*)d_in[9];
    const float* W3 = (const float*)d_in[10]; const float* b3 = (const float*)d_in[11];
    const float* Wout = (const float*)d_in[12];
    const float* bout = (const float*)d_in[13];
    float* out = (float*)d_out;

    void* z_addr = nullptr;
    cudaGetSymbolAddress(&z_addr, g_z);

    const int TB = 256;
    const int gemm_blocks   = (NN + 63) / 64;                 // 782
    const int gather_blocks = (NN * 32 + TB - 1) / TB;        // 6250

    cudaMemsetAsync(z_addr, 0, sizeof(ZeroBlk), 0);

    k_pre_deg <<<(NE + TB - 1) / TB, TB>>>(ei, ea);
    k_scan_block<<<NB, SCAN_B>>>();
    k_place<<<(NE + TB - 1) / TB, TB>>>(ei, ea);

    // layer 0: 128 -> 64 from x
    k_gemm<INCH, false><<<gemm_blocks, TB>>>(x, W0);
    k_gather<<<gather_blocks, TB>>>(b0);
    // layers 1..3: 64 -> 64 from g_act (already tanh'd), resolved in device code
    k_gemm<CH, true><<<gemm_blocks, TB>>>(nullptr, W1);
    k_gather<<<gather_blocks, TB>>>(b1);
    k_gemm<CH, true><<<gemm_blocks, TB>>>(nullptr, W2);
    k_gather<<<gather_blocks, TB>>>(b2);
    k_gemm<CH, true><<<gemm_blocks, TB>>>(nullptr, W3);
    k_gather<<<gather_blocks, TB>>>(b3);

    k_pool<<<gemm_blocks, TB>>>(batch, Wout, bout, out);
}